// round 15
// baseline (speedup 1.0000x reference)
#include <cuda_runtime.h>
#include <cuda_fp16.h>
#include <cstdint>

#define D 1024
#define B_TOK 16384
#define E_EXP 8
#define NSLOT (2 * B_TOK)
#define NKT16 (D / 16)          // 64 16-k groups (weight layout granularity)
#define NKT32 (D / 32)          // 32 pipeline iterations
#define STAGES 4
#define STAGE_BYTES 16384       // A 8K + B 8K
#define SMEM_BYTES (STAGES * STAGE_BYTES)

// ---------------- scratch: __device__ globals (no allocations allowed) ----------------
__device__ float  g_Wog[D * E_EXP];
__device__ float  g_Wvog[D * E_EXP];
__device__ float  g_beff[E_EXP];
__device__ int    g_tok_e[2 * B_TOK];
__device__ float  g_tok_w[2 * B_TOK];
__device__ int    g_tok_slot[2 * B_TOK];
__device__ int    g_counts[E_EXP];
__device__ int    g_offsets[E_EXP];
__device__ int    g_cursor[E_EXP];
__device__ double g_imp[E_EXP];
__device__ int    g_slot_tok[NSLOT];
__device__ float  g_slot_w[NSLOT];

// activations: single fp16, pair-permuted 16-groups
__device__ __align__(256) __half g_x[(size_t)B_TOK * D];
__device__ __align__(256) __half g_h1[(size_t)NSLOT * D];
// weights: single fp16, transposed [e][kt16][n][16] pair-permuted
__device__ __align__(256) __half g_w1[(size_t)E_EXP * NKT16 * D * 16];
__device__ __align__(256) __half g_w2[(size_t)E_EXP * NKT16 * D * 16];
// expert outputs (scaled), fp16, combined by k_combine
__device__ __align__(256) __half g_h2[(size_t)NSLOT * D];

// ---------------- streams/events (created before harness checkpoints) ----------------
struct HxStreams {
    cudaStream_t s1;
    cudaEvent_t ev0, ev1, ev2, evA, evB;
    HxStreams() {
        cudaStreamCreateWithFlags(&s1, cudaStreamNonBlocking);
        cudaEventCreateWithFlags(&ev0, cudaEventDisableTiming);
        cudaEventCreateWithFlags(&ev1, cudaEventDisableTiming);
        cudaEventCreateWithFlags(&ev2, cudaEventDisableTiming);
        cudaEventCreateWithFlags(&evA, cudaEventDisableTiming);
        cudaEventCreateWithFlags(&evB, cudaEventDisableTiming);
    }
};
static HxStreams g_hx;

// pair-permuted position of k within a 16-group: pairs stored (0,4,1,5,2,6,3,7)
__device__ __forceinline__ int perm16(int k) {
    int p = k >> 1;
    return (((p & 3) * 2 + (p >> 2)) << 1) + (k & 1);
}

__device__ __forceinline__ void cpa16(uint32_t saddr, const void* g) {
    asm volatile("cp.async.cg.shared.global [%0], [%1], 16;" :: "r"(saddr), "l"(g));
}
__device__ __forceinline__ void mma_f16(float* d, const uint32_t* a, const uint32_t* b) {
    asm("mma.sync.aligned.m16n8k16.row.col.f32.f16.f16.f32 "
        "{%0,%1,%2,%3},{%4,%5,%6,%7},{%8,%9},{%0,%1,%2,%3};"
        : "+f"(d[0]), "+f"(d[1]), "+f"(d[2]), "+f"(d[3])
        : "r"(a[0]), "r"(a[1]), "r"(a[2]), "r"(a[3]), "r"(b[0]), "r"(b[1]));
}

// ---------------- small mats for gating (fp32) ----------------
__global__ __launch_bounds__(256) void k_mat_small(const float* __restrict__ A,
                                                   const float* __restrict__ BmArg,
                                                   int which) {
    const float* Bm = (which == 0) ? BmArg : g_Wog;
    float* out = (which == 0) ? g_Wog : g_Wvog;
    int r = blockIdx.x;
    float acc[8];
#pragma unroll
    for (int e = 0; e < 8; e++) acc[e] = 0.f;
    for (int k = threadIdx.x; k < D; k += 256) {
        float a = A[(size_t)r * D + k];
        const float4* b4 = reinterpret_cast<const float4*>(Bm + (size_t)k * 8);
        float4 b0 = b4[0], b1 = b4[1];
        acc[0] += a * b0.x; acc[1] += a * b0.y; acc[2] += a * b0.z; acc[3] += a * b0.w;
        acc[4] += a * b1.x; acc[5] += a * b1.y; acc[6] += a * b1.z; acc[7] += a * b1.w;
    }
#pragma unroll
    for (int off = 16; off > 0; off >>= 1)
#pragma unroll
        for (int e = 0; e < 8; e++) acc[e] += __shfl_xor_sync(0xFFFFFFFFu, acc[e], off);
    __shared__ float sred[8][8];
    int warp = threadIdx.x >> 5, lane = threadIdx.x & 31;
    if (lane == 0)
#pragma unroll
        for (int e = 0; e < 8; e++) sred[warp][e] = acc[e];
    __syncthreads();
    if (threadIdx.x < 8) {
        float s = 0.f;
#pragma unroll
        for (int w = 0; w < 8; w++) s += sred[w][threadIdx.x];
        out[(size_t)r * 8 + threadIdx.x] = s;
    }
}

__global__ __launch_bounds__(256) void k_beff(const float* __restrict__ bv,
                                              const float* __restrict__ bo,
                                              const float* __restrict__ Wg,
                                              const float* __restrict__ bg) {
    float acc[8];
#pragma unroll
    for (int e = 0; e < 8; e++) acc[e] = 0.f;
    for (int k = threadIdx.x; k < D; k += 256) {
        float a = bv[k], b = bo[k];
        const float4* w4 = reinterpret_cast<const float4*>(g_Wog + (size_t)k * 8);
        const float4* g4 = reinterpret_cast<const float4*>(Wg + (size_t)k * 8);
        float4 w0 = w4[0], w1 = w4[1], g0 = g4[0], g1 = g4[1];
        acc[0] += a * w0.x + b * g0.x; acc[1] += a * w0.y + b * g0.y;
        acc[2] += a * w0.z + b * g0.z; acc[3] += a * w0.w + b * g0.w;
        acc[4] += a * w1.x + b * g1.x; acc[5] += a * w1.y + b * g1.y;
        acc[6] += a * w1.z + b * g1.z; acc[7] += a * w1.w + b * g1.w;
    }
#pragma unroll
    for (int off = 16; off > 0; off >>= 1)
#pragma unroll
        for (int e = 0; e < 8; e++) acc[e] += __shfl_xor_sync(0xFFFFFFFFu, acc[e], off);
    __shared__ float sred[8][8];
    int warp = threadIdx.x >> 5, lane = threadIdx.x & 31;
    if (lane == 0)
#pragma unroll
        for (int e = 0; e < 8; e++) sred[warp][e] = acc[e];
    __syncthreads();
    if (threadIdx.x < 8) {
        float s = 0.f;
#pragma unroll
        for (int w = 0; w < 8; w++) s += sred[w][threadIdx.x];
        g_beff[threadIdx.x] = s + bg[threadIdx.x];
    }
}

// ---------------- gating (fp32, selection-critical — unchanged) ----------------
__global__ __launch_bounds__(256) void k_gate(const float* __restrict__ q,
                                              float* __restrict__ gate_out) {
    int warp = threadIdx.x >> 5, lane = threadIdx.x & 31;
    int b = blockIdx.x * 8 + warp;
    const float* qrow = q + (size_t)b * D;
    float acc[8];
#pragma unroll
    for (int e = 0; e < 8; e++) acc[e] = 0.f;
#pragma unroll 4
    for (int i = 0; i < 32; i++) {
        int k = i * 32 + lane;
        float qa = qrow[k];
        const float4* w4 = reinterpret_cast<const float4*>(g_Wvog + (size_t)k * 8);
        float4 w0 = w4[0], w1 = w4[1];
        acc[0] += qa * w0.x; acc[1] += qa * w0.y; acc[2] += qa * w0.z; acc[3] += qa * w0.w;
        acc[4] += qa * w1.x; acc[5] += qa * w1.y; acc[6] += qa * w1.z; acc[7] += qa * w1.w;
    }
#pragma unroll
    for (int off = 16; off > 0; off >>= 1)
#pragma unroll
        for (int e = 0; e < 8; e++) acc[e] += __shfl_xor_sync(0xFFFFFFFFu, acc[e], off);

    __shared__ double simp[8];
    if (threadIdx.x < 8) simp[threadIdx.x] = 0.0;
    __syncthreads();

    if (lane == 0) {
        float l[8];
#pragma unroll
        for (int e = 0; e < 8; e++) l[e] = acc[e] + g_beff[e];
        float m = l[0];
#pragma unroll
        for (int e = 1; e < 8; e++) m = fmaxf(m, l[e]);
        float ex[8], Z = 0.f;
#pragma unroll
        for (int e = 0; e < 8; e++) { ex[e] = expf(l[e] - m); Z += ex[e]; }
        float p[8];
        float invZ = 1.f / Z;
#pragma unroll
        for (int e = 0; e < 8; e++) p[e] = ex[e] * invZ;
#pragma unroll
        for (int e = 0; e < 8; e++) gate_out[(size_t)b * 8 + e] = p[e];

        int e1 = 0;
#pragma unroll
        for (int e = 1; e < 8; e++) if (p[e] > p[e1]) e1 = e;
        int e2 = (e1 == 0) ? 1 : 0;
#pragma unroll
        for (int e = 0; e < 8; e++) if (e != e1 && p[e] > p[e2]) e2 = e;
        float t = expf(p[e2] - p[e1]);
        float inv = 1.f / (1.f + t);
        g_tok_e[2 * b] = e1;  g_tok_e[2 * b + 1] = e2;
        g_tok_w[2 * b] = inv; g_tok_w[2 * b + 1] = t * inv;
        atomicAdd(&g_counts[e1], 1);
        atomicAdd(&g_counts[e2], 1);
#pragma unroll
        for (int e = 0; e < 8; e++) atomicAdd(&simp[e], (double)p[e]);
    }
    __syncthreads();
    if (threadIdx.x < 8) atomicAdd(&g_imp[threadIdx.x], simp[threadIdx.x]);
}

// ---------------- scatter (computes offsets inline from g_counts) ----------------
__global__ __launch_bounds__(256) void k_scatter() {
    __shared__ int soff[E_EXP];
    if (threadIdx.x == 0) {
        int o = 0;
#pragma unroll
        for (int e = 0; e < 8; e++) { soff[e] = o; o += g_counts[e]; }
        if (blockIdx.x == 0)
#pragma unroll
            for (int e = 0; e < 8; e++) g_offsets[e] = soff[e];
    }
    __syncthreads();
    int b = blockIdx.x * 256 + threadIdx.x;
    if (b >= B_TOK) return;
#pragma unroll
    for (int j = 0; j < 2; j++) {
        int e = g_tok_e[2 * b + j];
        int s = soff[e] + atomicAdd(&g_cursor[e], 1);
        g_slot_tok[s] = b;
        g_slot_w[s] = g_tok_w[2 * b + j];
        g_tok_slot[2 * b + j] = s;
    }
}

// ---------------- convert x -> single fp16 (pair-permuted) + zero routing state ----------------
__global__ __launch_bounds__(256) void k_cvt_x(const float* __restrict__ x) {
    if (blockIdx.x == 0 && threadIdx.x < E_EXP) {
        g_counts[threadIdx.x] = 0;
        g_cursor[threadIdx.x] = 0;
        g_imp[threadIdx.x] = 0.0;
    }
    int id = blockIdx.x * 256 + threadIdx.x;          // tok*64 + grp
    int tok = id >> 6, grp = id & 63;
    const float* src = x + (size_t)tok * D + grp * 16;
    union { __half h[16]; uint4 u[2]; } o;
#pragma unroll
    for (int k = 0; k < 16; k++) o.h[perm16(k)] = __float2half_rn(src[k]);
    size_t off = (size_t)tok * D + grp * 16;
    reinterpret_cast<uint4*>(g_x + off)[0] = o.u[0];
    reinterpret_cast<uint4*>(g_x + off)[1] = o.u[1];
}

// ---------------- convert+transpose one weight tensor -> [e][kt16][n][16] fp16 ----------------
__global__ __launch_bounds__(256) void k_cvt_w(const float* __restrict__ W1,
                                               const float* __restrict__ W2,
                                               int which) {
    const float* W = (which == 0) ? W1 : W2;
    __half* wdst = (which == 0) ? g_w1 : g_w2;
    int id = blockIdx.x * 256 + threadIdx.x;          // e*64*1024 + kt*1024 + n
    int e = id >> 16, kt = (id >> 10) & 63, n = id & 1023;
    const float* src = W + ((size_t)e * D + kt * 16) * D + n;
    union { __half h[16]; uint4 u[2]; } o;
#pragma unroll
    for (int k = 0; k < 16; k++) o.h[perm16(k)] = __float2half_rn(src[(size_t)k * D]);
    size_t off = (size_t)id * 16;
    reinterpret_cast<uint4*>(wdst + off)[0] = o.u[0];
    reinterpret_cast<uint4*>(wdst + off)[1] = o.u[1];
}

// ---------------- grouped fp16 GEMM, single-pass, cp.async 4-stage, BK=32/iter ----------------
// 128x128 CTA tile, 8 warps (2Mx4N), warp tile 64x32, occupancy 2.
// Stage (u32 words): A[ks][row][8] (2x1024) then B[ks][row][8] (2x1024) -> 16KB.
// MODE 1: h1(fp16) = silu( gather(x) @ W1 + b1 )
// MODE 2: g_h2(fp16)[slot] = slot_w * ( h1 @ W2 + b2 )
template <int MODE>
__global__ __launch_bounds__(256, 2) void k_gemm(const float* __restrict__ bbase) {
    extern __shared__ uint32_t smem[];

    int e = blockIdx.z;
    int M = g_counts[e];
    int m0 = blockIdx.y * 128;
    if (m0 >= M) return;
    int n0 = blockIdx.x * 128;
    int goff = g_offsets[e];
    const float* bp = bbase + (size_t)e * D;

    const __half* Ag = (MODE == 1) ? g_x : g_h1;
    const __half* Bg = (MODE == 1) ? g_w1 : g_w2;

    int tid = threadIdx.x;
    int lane = tid & 31, warp = tid >> 5;
    int g = lane >> 2, c4 = lane & 3;
    int wm = warp >> 2, wn = warp & 3;

    // loader: thread -> (row rA, ks-half hf); each loads 32B of A and 32B of B per iter
    int rA = tid >> 1, hf = tid & 1;
    int rr = m0 + rA; if (rr > M - 1) rr = M - 1;
    const char* srcA;   // A row, 16-halves group hf of each 32-k chunk
    if (MODE == 1) srcA = (const char*)(Ag + (size_t)g_slot_tok[goff + rr] * D) + hf * 32;
    else           srcA = (const char*)(Ag + (size_t)(goff + rr) * D) + hf * 32;
    // B: kt16 = 2*kt + hf, row n0+rA: 32 bytes
    const char* srcB = (const char*)(Bg) +
        (((size_t)e * NKT16 + hf) * D + (size_t)(n0 + rA)) * 32;

    uint32_t sbase = (uint32_t)__cvta_generic_to_shared(smem);
    uint32_t wAd = sbase + (hf * 1024 + rA * 8) * 4;      // A dst
    uint32_t wBd = wAd + 8192;                            // B dst (+2048 u32)

#define ISSUE(kt, s)                                                          \
    do {                                                                      \
        uint32_t so = (s) * STAGE_BYTES;                                      \
        const char* ga = srcA + (size_t)(kt) * 64;                            \
        const char* gb = srcB + (size_t)(kt) * (D * 64);                      \
        cpa16(wAd + so, ga); cpa16(wAd + so + 16, ga + 16);                   \
        cpa16(wBd + so, gb); cpa16(wBd + so + 16, gb + 16);                   \
        asm volatile("cp.async.commit_group;");                               \
    } while (0)

    float acc[4][4][4];
#pragma unroll
    for (int mt = 0; mt < 4; mt++)
#pragma unroll
        for (int nt = 0; nt < 4; nt++)
#pragma unroll
            for (int i = 0; i < 4; i++) acc[mt][nt][i] = 0.f;

#pragma unroll
    for (int s = 0; s < STAGES - 1; s++) ISSUE(s, s);

    int aBase = (wm * 64 + g) * 8 + 2 * c4;
    int bBase = 2048 + (wn * 32 + g) * 8 + 2 * c4;

    for (int kt = 0; kt < NKT32; kt++) {
        int s = kt & 3;
        asm volatile("cp.async.wait_group 2;");
        __syncthreads();
        int pf = kt + STAGES - 1;
        if (pf < NKT32) ISSUE(pf, pf & 3);

        const uint32_t* stg = smem + s * (STAGE_BYTES / 4);
#pragma unroll
        for (int ks = 0; ks < 2; ks++) {
            const uint32_t* st = stg + ks * 1024;
            uint32_t bh[4][2];
#pragma unroll
            for (int nt = 0; nt < 4; nt++) {
                uint2 vh = *reinterpret_cast<const uint2*>(st + bBase + nt * 64);
                bh[nt][0] = vh.x; bh[nt][1] = vh.y;
            }
#pragma unroll
            for (int mt = 0; mt < 4; mt++) {
                const uint32_t* pa = st + aBase + mt * 128;
                uint2 h0 = *reinterpret_cast<const uint2*>(pa);
                uint2 h1 = *reinterpret_cast<const uint2*>(pa + 64);
                uint32_t ah[4] = {h0.x, h1.x, h0.y, h1.y};
#pragma unroll
                for (int nt = 0; nt < 4; nt++) {
                    mma_f16(acc[mt][nt], ah, bh[nt]);
                }
            }
        }
    }
#undef ISSUE

    // ---------------- epilogue ----------------
#pragma unroll
    for (int nt = 0; nt < 4; nt++) {
        int j = n0 + wn * 32 + nt * 8 + 2 * c4;      // even col pair (j, j+1)
        float2 bb = *reinterpret_cast<const float2*>(bp + j);
        int grp = j >> 4;
        int pidx = grp * 16 + perm16(j & 15);        // permuted element index of col j
#pragma unroll
        for (int mt = 0; mt < 4; mt++) {
            int r0 = m0 + wm * 64 + mt * 16 + g;
#pragma unroll
            for (int half = 0; half < 2; half++) {
                int gr = r0 + half * 8;
                if (gr >= M) continue;
                float z0 = acc[mt][nt][2 * half] + bb.x;
                float z1 = acc[mt][nt][2 * half + 1] + bb.y;
                if (MODE == 1) {
                    float s0 = z0 / (1.f + expf(-z0));
                    float s1 = z1 / (1.f + expf(-z1));
                    size_t off = (size_t)(goff + gr) * D + pidx;
                    *reinterpret_cast<__half2*>(g_h1 + off) = __floats2half2_rn(s0, s1);
                } else {
                    float wr = g_slot_w[goff + gr];
                    *reinterpret_cast<__half2*>(g_h2 + (size_t)(goff + gr) * D + j) =
                        __floats2half2_rn(wr * z0, wr * z1);
                }
            }
        }
    }
}

// ---------------- combine: y[b] = h2[slot(b,0)] + h2[slot(b,1)]; block 0 also writes loss ----------------
__global__ __launch_bounds__(256) void k_combine(float* __restrict__ y,
                                                 float* __restrict__ loss_out) {
    if (blockIdx.x == 0 && threadIdx.x == 0) {
        double s = 0.0;
#pragma unroll
        for (int e = 0; e < 8; e++) s += g_imp[e];
        double mean = s / 8.0;
        double var = 0.0;
#pragma unroll
        for (int e = 0; e < 8; e++) { double d = g_imp[e] - mean; var += d * d; }
        var /= 7.0;
        loss_out[0] = (float)(0.01 * var / (mean * mean));
    }
    int idx = blockIdx.x * 256 + threadIdx.x;     // over B*D/8 chunks of 8 halves
    int b = idx >> 7;                             // D/8 = 128 chunks per row
    int c = idx & 127;
    const uint4* h2 = reinterpret_cast<const uint4*>(g_h2);
    uint4 ua = h2[(size_t)g_tok_slot[2 * b] * 128 + c];
    uint4 ub = h2[(size_t)g_tok_slot[2 * b + 1] * 128 + c];
    const __half2* pa = reinterpret_cast<const __half2*>(&ua);
    const __half2* pb = reinterpret_cast<const __half2*>(&ub);
    float4 o0, o1;
    float2 s;
    s = __half22float2(pa[0]); { float2 t = __half22float2(pb[0]); o0.x = s.x + t.x; o0.y = s.y + t.y; }
    s = __half22float2(pa[1]); { float2 t = __half22float2(pb[1]); o0.z = s.x + t.x; o0.w = s.y + t.y; }
    s = __half22float2(pa[2]); { float2 t = __half22float2(pb[2]); o1.x = s.x + t.x; o1.y = s.y + t.y; }
    s = __half22float2(pa[3]); { float2 t = __half22float2(pb[3]); o1.z = s.x + t.x; o1.w = s.y + t.y; }
    float4* dst = reinterpret_cast<float4*>(y + (size_t)idx * 8);
    dst[0] = o0;
    dst[1] = o1;
}

extern "C" void kernel_launch(void* const* d_in, const int* in_sizes, int n_in,
                              void* d_out, int out_size) {
    const float* x  = (const float*)d_in[0];
    const float* q  = (const float*)d_in[1];
    const float* Wv = (const float*)d_in[2];
    const float* bv = (const float*)d_in[3];
    const float* Wo = (const float*)d_in[4];
    const float* bo = (const float*)d_in[5];
    const float* Wg = (const float*)d_in[6];
    const float* bg = (const float*)d_in[7];
    const float* W1 = (const float*)d_in[8];
    const float* b1 = (const float*)d_in[9];
    const float* W2 = (const float*)d_in[10];
    const float* b2 = (const float*)d_in[11];

    float* y        = (float*)d_out;
    float* gate_out = y + (size_t)B_TOK * D;
    float* loss_out = gate_out + (size_t)B_TOK * E_EXP;

    static int smem_set = 0;
    if (!smem_set) {
        cudaFuncSetAttribute(k_gemm<1>, cudaFuncAttributeMaxDynamicSharedMemorySize, SMEM_BYTES);
        cudaFuncSetAttribute(k_gemm<2>, cudaFuncAttributeMaxDynamicSharedMemorySize, SMEM_BYTES);
        smem_set = 1;
    }

    const int WGRID = (E_EXP * NKT16 * D) / 256;

    // side stream: weight conversion
    cudaEventRecord(g_hx.ev0, 0);
    cudaStreamWaitEvent(g_hx.s1, g_hx.ev0, 0);
    k_cvt_w<<<WGRID, 256, 0, g_hx.s1>>>(W1, W2, 0);
    cudaEventRecord(g_hx.ev1, g_hx.s1);
    k_cvt_w<<<WGRID, 256, 0, g_hx.s1>>>(W1, W2, 1);
    cudaEventRecord(g_hx.ev2, g_hx.s1);

    // main stream: activation conversion + gating chain
    k_cvt_x<<<(B_TOK * 64) / 256, 256>>>(x);   // also zeroes routing state (block 0)
    k_mat_small<<<D, 256>>>(Wo, Wg, 0);
    cudaEventRecord(g_hx.evA, 0);
    cudaStreamWaitEvent(g_hx.s1, g_hx.evA, 0);
    k_beff<<<1, 256, 0, g_hx.s1>>>(bv, bo, Wg, bg);
    cudaEventRecord(g_hx.evB, g_hx.s1);
    k_mat_small<<<D, 256>>>(Wv, nullptr, 1);
    cudaStreamWaitEvent(0, g_hx.evB, 0);
    k_gate<<<B_TOK / 8, 256>>>(q, gate_out);
    k_scatter<<<B_TOK / 256, 256>>>();

    cudaStreamWaitEvent(0, g_hx.ev1, 0);       // W1 ready
    k_gemm<1><<<dim3(D / 128, B_TOK / 128, E_EXP), 256, SMEM_BYTES>>>(b1);
    cudaStreamWaitEvent(0, g_hx.ev2, 0);       // W2 ready
    k_gemm<2><<<dim3(D / 128, B_TOK / 128, E_EXP), 256, SMEM_BYTES>>>(b2);
    k_combine<<<(B_TOK * D / 8) / 256, 256>>>(y, loss_out);
}

// round 16
// speedup vs baseline: 1.2410x; 1.2410x over previous
#include <cuda_runtime.h>
#include <cuda_fp16.h>
#include <cstdint>

#define D 1024
#define B_TOK 16384
#define E_EXP 8
#define NSLOT (2 * B_TOK)
#define NKT (D / 16)            // 64 k-tiles
#define STAGES 8
#define STAGE_BYTES 8192        // A 4K + B 4K
#define SMEM_BYTES (STAGES * STAGE_BYTES)

// ---------------- scratch: __device__ globals (no allocations allowed) ----------------
__device__ float  g_Wog[D * E_EXP];
__device__ float  g_Wvog[D * E_EXP];
__device__ float  g_beff[E_EXP];
__device__ int    g_tok_e[2 * B_TOK];
__device__ float  g_tok_w[2 * B_TOK];
__device__ int    g_tok_slot[2 * B_TOK];
__device__ int    g_counts[E_EXP];
__device__ int    g_offsets[E_EXP];
__device__ int    g_cursor[E_EXP];
__device__ double g_imp[E_EXP];
__device__ int    g_slot_tok[NSLOT];
__device__ float  g_slot_w[NSLOT];

// activations: single fp16, pair-permuted 16-groups
__device__ __align__(256) __half g_x[(size_t)B_TOK * D];
__device__ __align__(256) __half g_h1[(size_t)NSLOT * D];
// weights: single fp16, transposed [e][kt][n][16] pair-permuted
__device__ __align__(256) __half g_w1[(size_t)E_EXP * NKT * D * 16];
__device__ __align__(256) __half g_w2[(size_t)E_EXP * NKT * D * 16];
// expert outputs (scaled), fp16, combined by k_combine
__device__ __align__(256) __half g_h2[(size_t)NSLOT * D];

// ---------------- streams/events (created before harness checkpoints) ----------------
struct HxStreams {
    cudaStream_t s1;
    cudaEvent_t ev0, ev1, ev2, evA, evB;
    HxStreams() {
        cudaStreamCreateWithFlags(&s1, cudaStreamNonBlocking);
        cudaEventCreateWithFlags(&ev0, cudaEventDisableTiming);
        cudaEventCreateWithFlags(&ev1, cudaEventDisableTiming);
        cudaEventCreateWithFlags(&ev2, cudaEventDisableTiming);
        cudaEventCreateWithFlags(&evA, cudaEventDisableTiming);
        cudaEventCreateWithFlags(&evB, cudaEventDisableTiming);
    }
};
static HxStreams g_hx;

// pair-permuted position of k within a 16-group: pairs stored (0,4,1,5,2,6,3,7)
__device__ __forceinline__ int perm16(int k) {
    int p = k >> 1;
    return (((p & 3) * 2 + (p >> 2)) << 1) + (k & 1);
}

__device__ __forceinline__ void cpa16(uint32_t saddr, const void* g) {
    asm volatile("cp.async.cg.shared.global [%0], [%1], 16;" :: "r"(saddr), "l"(g));
}
__device__ __forceinline__ void mma_f16(float* d, const uint32_t* a, const uint32_t* b) {
    asm("mma.sync.aligned.m16n8k16.row.col.f32.f16.f16.f32 "
        "{%0,%1,%2,%3},{%4,%5,%6,%7},{%8,%9},{%0,%1,%2,%3};"
        : "+f"(d[0]), "+f"(d[1]), "+f"(d[2]), "+f"(d[3])
        : "r"(a[0]), "r"(a[1]), "r"(a[2]), "r"(a[3]), "r"(b[0]), "r"(b[1]));
}

// ---------------- small mats for gating (fp32) ----------------
__global__ __launch_bounds__(256) void k_mat_small(const float* __restrict__ A,
                                                   const float* __restrict__ BmArg,
                                                   int which) {
    const float* Bm = (which == 0) ? BmArg : g_Wog;
    float* out = (which == 0) ? g_Wog : g_Wvog;
    int r = blockIdx.x;
    float acc[8];
#pragma unroll
    for (int e = 0; e < 8; e++) acc[e] = 0.f;
    for (int k = threadIdx.x; k < D; k += 256) {
        float a = A[(size_t)r * D + k];
        const float4* b4 = reinterpret_cast<const float4*>(Bm + (size_t)k * 8);
        float4 b0 = b4[0], b1 = b4[1];
        acc[0] += a * b0.x; acc[1] += a * b0.y; acc[2] += a * b0.z; acc[3] += a * b0.w;
        acc[4] += a * b1.x; acc[5] += a * b1.y; acc[6] += a * b1.z; acc[7] += a * b1.w;
    }
#pragma unroll
    for (int off = 16; off > 0; off >>= 1)
#pragma unroll
        for (int e = 0; e < 8; e++) acc[e] += __shfl_xor_sync(0xFFFFFFFFu, acc[e], off);
    __shared__ float sred[8][8];
    int warp = threadIdx.x >> 5, lane = threadIdx.x & 31;
    if (lane == 0)
#pragma unroll
        for (int e = 0; e < 8; e++) sred[warp][e] = acc[e];
    __syncthreads();
    if (threadIdx.x < 8) {
        float s = 0.f;
#pragma unroll
        for (int w = 0; w < 8; w++) s += sred[w][threadIdx.x];
        out[(size_t)r * 8 + threadIdx.x] = s;
    }
}

__global__ __launch_bounds__(256) void k_beff(const float* __restrict__ bv,
                                              const float* __restrict__ bo,
                                              const float* __restrict__ Wg,
                                              const float* __restrict__ bg) {
    float acc[8];
#pragma unroll
    for (int e = 0; e < 8; e++) acc[e] = 0.f;
    for (int k = threadIdx.x; k < D; k += 256) {
        float a = bv[k], b = bo[k];
        const float4* w4 = reinterpret_cast<const float4*>(g_Wog + (size_t)k * 8);
        const float4* g4 = reinterpret_cast<const float4*>(Wg + (size_t)k * 8);
        float4 w0 = w4[0], w1 = w4[1], g0 = g4[0], g1 = g4[1];
        acc[0] += a * w0.x + b * g0.x; acc[1] += a * w0.y + b * g0.y;
        acc[2] += a * w0.z + b * g0.z; acc[3] += a * w0.w + b * g0.w;
        acc[4] += a * w1.x + b * g1.x; acc[5] += a * w1.y + b * g1.y;
        acc[6] += a * w1.z + b * g1.z; acc[7] += a * w1.w + b * g1.w;
    }
#pragma unroll
    for (int off = 16; off > 0; off >>= 1)
#pragma unroll
        for (int e = 0; e < 8; e++) acc[e] += __shfl_xor_sync(0xFFFFFFFFu, acc[e], off);
    __shared__ float sred[8][8];
    int warp = threadIdx.x >> 5, lane = threadIdx.x & 31;
    if (lane == 0)
#pragma unroll
        for (int e = 0; e < 8; e++) sred[warp][e] = acc[e];
    __syncthreads();
    if (threadIdx.x < 8) {
        float s = 0.f;
#pragma unroll
        for (int w = 0; w < 8; w++) s += sred[w][threadIdx.x];
        g_beff[threadIdx.x] = s + bg[threadIdx.x];
    }
}

// ---------------- gating (fp32, selection-critical — unchanged) ----------------
__global__ __launch_bounds__(256) void k_gate(const float* __restrict__ q,
                                              float* __restrict__ gate_out) {
    int warp = threadIdx.x >> 5, lane = threadIdx.x & 31;
    int b = blockIdx.x * 8 + warp;
    const float* qrow = q + (size_t)b * D;
    float acc[8];
#pragma unroll
    for (int e = 0; e < 8; e++) acc[e] = 0.f;
#pragma unroll 4
    for (int i = 0; i < 32; i++) {
        int k = i * 32 + lane;
        float qa = qrow[k];
        const float4* w4 = reinterpret_cast<const float4*>(g_Wvog + (size_t)k * 8);
        float4 w0 = w4[0], w1 = w4[1];
        acc[0] += qa * w0.x; acc[1] += qa * w0.y; acc[2] += qa * w0.z; acc[3] += qa * w0.w;
        acc[4] += qa * w1.x; acc[5] += qa * w1.y; acc[6] += qa * w1.z; acc[7] += qa * w1.w;
    }
#pragma unroll
    for (int off = 16; off > 0; off >>= 1)
#pragma unroll
        for (int e = 0; e < 8; e++) acc[e] += __shfl_xor_sync(0xFFFFFFFFu, acc[e], off);

    __shared__ double simp[8];
    if (threadIdx.x < 8) simp[threadIdx.x] = 0.0;
    __syncthreads();

    if (lane == 0) {
        float l[8];
#pragma unroll
        for (int e = 0; e < 8; e++) l[e] = acc[e] + g_beff[e];
        float m = l[0];
#pragma unroll
        for (int e = 1; e < 8; e++) m = fmaxf(m, l[e]);
        float ex[8], Z = 0.f;
#pragma unroll
        for (int e = 0; e < 8; e++) { ex[e] = expf(l[e] - m); Z += ex[e]; }
        float p[8];
        float invZ = 1.f / Z;
#pragma unroll
        for (int e = 0; e < 8; e++) p[e] = ex[e] * invZ;
#pragma unroll
        for (int e = 0; e < 8; e++) gate_out[(size_t)b * 8 + e] = p[e];

        int e1 = 0;
#pragma unroll
        for (int e = 1; e < 8; e++) if (p[e] > p[e1]) e1 = e;
        int e2 = (e1 == 0) ? 1 : 0;
#pragma unroll
        for (int e = 0; e < 8; e++) if (e != e1 && p[e] > p[e2]) e2 = e;
        float t = expf(p[e2] - p[e1]);
        float inv = 1.f / (1.f + t);
        g_tok_e[2 * b] = e1;  g_tok_e[2 * b + 1] = e2;
        g_tok_w[2 * b] = inv; g_tok_w[2 * b + 1] = t * inv;
        atomicAdd(&g_counts[e1], 1);
        atomicAdd(&g_counts[e2], 1);
#pragma unroll
        for (int e = 0; e < 8; e++) atomicAdd(&simp[e], (double)p[e]);
    }
    __syncthreads();
    if (threadIdx.x < 8) atomicAdd(&g_imp[threadIdx.x], simp[threadIdx.x]);
}

// ---------------- scatter (computes offsets inline from g_counts; no k_scan) ----------------
__global__ __launch_bounds__(256) void k_scatter() {
    __shared__ int soff[E_EXP];
    if (threadIdx.x == 0) {
        int o = 0;
#pragma unroll
        for (int e = 0; e < 8; e++) { soff[e] = o; o += g_counts[e]; }
        if (blockIdx.x == 0)
#pragma unroll
            for (int e = 0; e < 8; e++) g_offsets[e] = soff[e];
    }
    __syncthreads();
    int b = blockIdx.x * 256 + threadIdx.x;
    if (b >= B_TOK) return;
#pragma unroll
    for (int j = 0; j < 2; j++) {
        int e = g_tok_e[2 * b + j];
        int s = soff[e] + atomicAdd(&g_cursor[e], 1);
        g_slot_tok[s] = b;
        g_slot_w[s] = g_tok_w[2 * b + j];
        g_tok_slot[2 * b + j] = s;
    }
}

// ---------------- convert x -> single fp16 (pair-permuted) + zero routing state ----------------
__global__ __launch_bounds__(256) void k_cvt_x(const float* __restrict__ x) {
    if (blockIdx.x == 0 && threadIdx.x < E_EXP) {
        g_counts[threadIdx.x] = 0;
        g_cursor[threadIdx.x] = 0;
        g_imp[threadIdx.x] = 0.0;
    }
    int id = blockIdx.x * 256 + threadIdx.x;          // tok*64 + grp
    int tok = id >> 6, grp = id & 63;
    const float* src = x + (size_t)tok * D + grp * 16;
    union { __half h[16]; uint4 u[2]; } o;
#pragma unroll
    for (int k = 0; k < 16; k++) o.h[perm16(k)] = __float2half_rn(src[k]);
    size_t off = (size_t)tok * D + grp * 16;
    reinterpret_cast<uint4*>(g_x + off)[0] = o.u[0];
    reinterpret_cast<uint4*>(g_x + off)[1] = o.u[1];
}

// ---------------- convert+transpose one weight tensor -> [e][kt][n][16] fp16 ----------------
__global__ __launch_bounds__(256) void k_cvt_w(const float* __restrict__ W1,
                                               const float* __restrict__ W2,
                                               int which) {
    const float* W = (which == 0) ? W1 : W2;
    __half* wdst = (which == 0) ? g_w1 : g_w2;
    int id = blockIdx.x * 256 + threadIdx.x;          // e*64*1024 + kt*1024 + n
    int e = id >> 16, kt = (id >> 10) & 63, n = id & 1023;
    const float* src = W + ((size_t)e * D + kt * 16) * D + n;
    union { __half h[16]; uint4 u[2]; } o;
#pragma unroll
    for (int k = 0; k < 16; k++) o.h[perm16(k)] = __float2half_rn(src[(size_t)k * D]);
    size_t off = (size_t)id * 16;
    reinterpret_cast<uint4*>(wdst + off)[0] = o.u[0];
    reinterpret_cast<uint4*>(wdst + off)[1] = o.u[1];
}

// ---------------- grouped fp16 GEMM, single-pass, cp.async 8-stage ----------------
// 128x128 CTA tile, BK=16, 8 warps (2Mx4N), warp tile 64x32, occupancy 2.
// MODE 1: h1(fp16) = silu( gather(x) @ W1 + b1 )
// MODE 2: g_h2(fp16)[slot] = slot_w * ( h1 @ W2 + b2 )
template <int MODE>
__global__ __launch_bounds__(256, 2) void k_gemm(const float* __restrict__ bbase) {
    extern __shared__ uint32_t smem[];

    int e = blockIdx.z;
    int M = g_counts[e];
    int m0 = blockIdx.y * 128;
    if (m0 >= M) return;
    int n0 = blockIdx.x * 128;
    int goff = g_offsets[e];
    const float* bp = bbase + (size_t)e * D;

    const __half* Ag = (MODE == 1) ? g_x : g_h1;
    const __half* Bg = (MODE == 1) ? g_w1 : g_w2;

    int tid = threadIdx.x;
    int lane = tid & 31, warp = tid >> 5;
    int g = lane >> 2, c4 = lane & 3;
    int wm = warp >> 2, wn = warp & 3;

    // loader: thread -> (row = tid>>1, 16B half = tid&1) for both planes
    int rA = tid >> 1, hf = tid & 1;
    int rr = m0 + rA; if (rr > M - 1) rr = M - 1;
    const char* srcA;
    if (MODE == 1) srcA = (const char*)(Ag + (size_t)g_slot_tok[goff + rr] * D) + hf * 16;
    else           srcA = (const char*)(Ag + (size_t)(goff + rr) * D) + hf * 16;
    const char* srcB = (const char*)(Bg + (((size_t)e * NKT) * D + n0 + rA) * 16) + hf * 16;

    uint32_t sbase = (uint32_t)__cvta_generic_to_shared(smem);
    uint32_t wA = sbase + tid * 16;

#define ISSUE(kt, s)                                                          \
    do {                                                                      \
        uint32_t so = (s) * STAGE_BYTES;                                      \
        cpa16(wA + so, srcA + (kt) * 32);                                     \
        cpa16(wA + so + 4096, srcB + (size_t)(kt) * (D * 32));                \
        asm volatile("cp.async.commit_group;");                               \
    } while (0)

    float acc[4][4][4];
#pragma unroll
    for (int mt = 0; mt < 4; mt++)
#pragma unroll
        for (int nt = 0; nt < 4; nt++)
#pragma unroll
            for (int i = 0; i < 4; i++) acc[mt][nt][i] = 0.f;

#pragma unroll
    for (int s = 0; s < STAGES - 1; s++) ISSUE(s, s);

    int aBase = (wm * 64 + g) * 8 + 2 * c4;
    int bBase = 1024 + (wn * 32 + g) * 8 + 2 * c4;

    for (int kt = 0; kt < NKT; kt++) {
        int s = kt % STAGES;
        asm volatile("cp.async.wait_group 6;");
        __syncthreads();
        int pf = kt + STAGES - 1;
        if (pf < NKT) ISSUE(pf, pf % STAGES);

        const uint32_t* st = smem + s * (STAGE_BYTES / 4);
        uint32_t bh[4][2];
#pragma unroll
        for (int nt = 0; nt < 4; nt++) {
            uint2 vh = *reinterpret_cast<const uint2*>(st + bBase + nt * 64);
            bh[nt][0] = vh.x; bh[nt][1] = vh.y;
        }
#pragma unroll
        for (int mt = 0; mt < 4; mt++) {
            const uint32_t* pa = st + aBase + mt * 128;
            uint2 h0 = *reinterpret_cast<const uint2*>(pa);
            uint2 h1 = *reinterpret_cast<const uint2*>(pa + 64);
            uint32_t ah[4] = {h0.x, h1.x, h0.y, h1.y};
#pragma unroll
            for (int nt = 0; nt < 4; nt++) {
                mma_f16(acc[mt][nt], ah, bh[nt]);
            }
        }
    }
#undef ISSUE

    // ---------------- epilogue ----------------
#pragma unroll
    for (int nt = 0; nt < 4; nt++) {
        int j = n0 + wn * 32 + nt * 8 + 2 * c4;      // even col pair (j, j+1)
        float2 bb = *reinterpret_cast<const float2*>(bp + j);
        int grp = j >> 4;
        int pidx = grp * 16 + perm16(j & 15);        // permuted element index of col j
#pragma unroll
        for (int mt = 0; mt < 4; mt++) {
            int r0 = m0 + wm * 64 + mt * 16 + g;
#pragma unroll
            for (int half = 0; half < 2; half++) {
                int gr = r0 + half * 8;
                if (gr >= M) continue;
                float z0 = acc[mt][nt][2 * half] + bb.x;
                float z1 = acc[mt][nt][2 * half + 1] + bb.y;
                if (MODE == 1) {
                    float s0 = z0 / (1.f + expf(-z0));
                    float s1 = z1 / (1.f + expf(-z1));
                    size_t off = (size_t)(goff + gr) * D + pidx;
                    *reinterpret_cast<__half2*>(g_h1 + off) = __floats2half2_rn(s0, s1);
                } else {
                    float wr = g_slot_w[goff + gr];
                    *reinterpret_cast<__half2*>(g_h2 + (size_t)(goff + gr) * D + j) =
                        __floats2half2_rn(wr * z0, wr * z1);
                }
            }
        }
    }
}

// ---------------- combine: y[b] = h2[slot(b,0)] + h2[slot(b,1)]; block 0 also writes loss ----------------
__global__ __launch_bounds__(256) void k_combine(float* __restrict__ y,
                                                 float* __restrict__ loss_out) {
    if (blockIdx.x == 0 && threadIdx.x == 0) {
        double s = 0.0;
#pragma unroll
        for (int e = 0; e < 8; e++) s += g_imp[e];
        double mean = s / 8.0;
        double var = 0.0;
#pragma unroll
        for (int e = 0; e < 8; e++) { double d = g_imp[e] - mean; var += d * d; }
        var /= 7.0;
        loss_out[0] = (float)(0.01 * var / (mean * mean));
    }
    int idx = blockIdx.x * 256 + threadIdx.x;     // over B*D/8 chunks of 8 halves
    int b = idx >> 7;                             // D/8 = 128 chunks per row
    int c = idx & 127;
    const uint4* h2 = reinterpret_cast<const uint4*>(g_h2);
    uint4 ua = h2[(size_t)g_tok_slot[2 * b] * 128 + c];
    uint4 ub = h2[(size_t)g_tok_slot[2 * b + 1] * 128 + c];
    const __half2* pa = reinterpret_cast<const __half2*>(&ua);
    const __half2* pb = reinterpret_cast<const __half2*>(&ub);
    float4 o0, o1;
    float2 s;
    s = __half22float2(pa[0]); { float2 t = __half22float2(pb[0]); o0.x = s.x + t.x; o0.y = s.y + t.y; }
    s = __half22float2(pa[1]); { float2 t = __half22float2(pb[1]); o0.z = s.x + t.x; o0.w = s.y + t.y; }
    s = __half22float2(pa[2]); { float2 t = __half22float2(pb[2]); o1.x = s.x + t.x; o1.y = s.y + t.y; }
    s = __half22float2(pa[3]); { float2 t = __half22float2(pb[3]); o1.z = s.x + t.x; o1.w = s.y + t.y; }
    float4* dst = reinterpret_cast<float4*>(y + (size_t)idx * 8);
    dst[0] = o0;
    dst[1] = o1;
}

extern "C" void kernel_launch(void* const* d_in, const int* in_sizes, int n_in,
                              void* d_out, int out_size) {
    const float* x  = (const float*)d_in[0];
    const float* q  = (const float*)d_in[1];
    const float* Wv = (const float*)d_in[2];
    const float* bv = (const float*)d_in[3];
    const float* Wo = (const float*)d_in[4];
    const float* bo = (const float*)d_in[5];
    const float* Wg = (const float*)d_in[6];
    const float* bg = (const float*)d_in[7];
    const float* W1 = (const float*)d_in[8];
    const float* b1 = (const float*)d_in[9];
    const float* W2 = (const float*)d_in[10];
    const float* b2 = (const float*)d_in[11];

    float* y        = (float*)d_out;
    float* gate_out = y + (size_t)B_TOK * D;
    float* loss_out = gate_out + (size_t)B_TOK * E_EXP;

    static int smem_set = 0;
    if (!smem_set) {
        cudaFuncSetAttribute(k_gemm<1>, cudaFuncAttributeMaxDynamicSharedMemorySize, SMEM_BYTES);
        cudaFuncSetAttribute(k_gemm<2>, cudaFuncAttributeMaxDynamicSharedMemorySize, SMEM_BYTES);
        smem_set = 1;
    }

    const int WGRID = (E_EXP * NKT * D) / 256;

    // side stream: weight conversion
    cudaEventRecord(g_hx.ev0, 0);
    cudaStreamWaitEvent(g_hx.s1, g_hx.ev0, 0);
    k_cvt_w<<<WGRID, 256, 0, g_hx.s1>>>(W1, W2, 0);
    cudaEventRecord(g_hx.ev1, g_hx.s1);
    k_cvt_w<<<WGRID, 256, 0, g_hx.s1>>>(W1, W2, 1);
    cudaEventRecord(g_hx.ev2, g_hx.s1);

    // main stream: activation conversion + gating chain
    k_cvt_x<<<(B_TOK * 64) / 256, 256>>>(x);   // also zeroes routing state (block 0)
    k_mat_small<<<D, 256>>>(Wo, Wg, 0);
    cudaEventRecord(g_hx.evA, 0);
    cudaStreamWaitEvent(g_hx.s1, g_hx.evA, 0);
    k_beff<<<1, 256, 0, g_hx.s1>>>(bv, bo, Wg, bg);
    cudaEventRecord(g_hx.evB, g_hx.s1);
    k_mat_small<<<D, 256>>>(Wv, nullptr, 1);
    cudaStreamWaitEvent(0, g_hx.evB, 0);
    k_gate<<<B_TOK / 8, 256>>>(q, gate_out);
    k_scatter<<<B_TOK / 256, 256>>>();

    cudaStreamWaitEvent(0, g_hx.ev1, 0);       // W1 ready
    k_gemm<1><<<dim3(D / 128, B_TOK / 128, E_EXP), 256, SMEM_BYTES>>>(b1);
    cudaStreamWaitEvent(0, g_hx.ev2, 0);       // W2 ready
    k_gemm<2><<<dim3(D / 128, B_TOK / 128, E_EXP), 256, SMEM_BYTES>>>(b2);
    k_combine<<<(B_TOK * D / 8) / 256, 256>>>(y, loss_out);
}